// round 7
// baseline (speedup 1.0000x reference)
#include <cuda_runtime.h>

// Problem constants
#define NCH   8192
#define NTT   4096
#define NLAGS 103
#define RAWS  112
#define XCOR_N (NCH * NLAGS)

// Stage-1 tiling: 4 warps x 28 lags, 8 t per lane, swizzled smem
#define NWARP 4
#define LPW   28                    // lags per warp (4*28 = 112 >= 103)
#define ITERS (NTT / (8 * 32))      // 16 iterations, 256 t per warp-iter
#define A_FLOATS 4224               // 51 zero pad + 4096 + tail pad (128B mult)
#define B_FLOATS 4096

// Raw (pre-moving-average) cross-correlation scratch: 8192 x 112 f32 (~3.67MB, L2-resident)
__device__ float g_raw[(size_t)NCH * RAWS];

// ---------------------------------------------------------------------------
// Swizzle: permute 16B chunks so stride-32B lane access is bank-conflict-free.
// Toggles byte-addr bit4 based on bit7 (chunk bit0 based on chunk bit3).
// ---------------------------------------------------------------------------
__device__ __forceinline__ int swz(int byteoff) {
    return byteoff ^ ((byteoff >> 3) & 0x10);
}

// f32x2 packed helpers (sm_103a FFMA2: 2 FMAs per issue on the fma pipe)
__device__ __forceinline__ unsigned long long pack2(float lo, float hi) {
    unsigned long long r;
    asm("mov.b64 %0, {%1, %2};" : "=l"(r) : "f"(lo), "f"(hi));
    return r;
}
__device__ __forceinline__ void unpack2(unsigned long long v, float& lo, float& hi) {
    asm("mov.b64 {%0, %1}, %2;" : "=f"(lo), "=f"(hi) : "l"(v));
}
__device__ __forceinline__ void fma2(unsigned long long& d,
                                     unsigned long long a, unsigned long long b) {
    asm("fma.rn.f32x2 %0, %1, %2, %0;" : "+l"(d) : "l"(a), "l"(b));
}

// ---------------------------------------------------------------------------
// Stage 1: per-channel cross-correlation, R[c][l] = sum_t d1[c][t+l-51]*d2[c][t]
// Block = 1 channel, 128 threads. Warp w owns lags [28w, 28w+28).
// Lane handles 8 consecutive t per iter; lag pairs accumulate via fma.rn.f32x2.
// ---------------------------------------------------------------------------
__global__ __launch_bounds__(128, 4)
void xcorr_stage1(const float* __restrict__ d1, const float* __restrict__ d2)
{
    __shared__ __align__(128) float a_sm[A_FLOATS];
    __shared__ __align__(128) float b_sm[B_FLOATS];
    char* a_b = (char*)a_sm;
    char* b_b = (char*)b_sm;

    const int c   = blockIdx.x;
    const int tid = threadIdx.x;
    const float* __restrict__ r1 = d1 + (size_t)c * NTT;
    const float* __restrict__ r2 = d2 + (size_t)c * NTT;

    // Fill a (zero-padded by 51 at front, zeros at tail), scalar swizzled stores.
    for (int i = tid; i < A_FLOATS; i += 128) {
        float v = 0.0f;
        if (i >= 51 && i < 51 + NTT) v = r1[i - 51];
        *reinterpret_cast<float*>(a_b + swz(i * 4)) = v;
    }
    // Fill b, float4 swizzled (chunk-aligned so vector stores are safe).
    for (int k = tid; k < NTT / 4; k += 128) {
        float4 v = reinterpret_cast<const float4*>(r2)[k];
        *reinterpret_cast<float4*>(b_b + swz(k * 16)) = v;
    }
    __syncthreads();

    const int warp = tid >> 5;
    const int lane = tid & 31;
    const int lb   = warp * LPW;

    unsigned long long acc[LPW / 2];
#pragma unroll
    for (int j = 0; j < LPW / 2; ++j) acc[j] = 0ull;

#pragma unroll 1
    for (int it = 0; it < ITERS; ++it) {
        const int tb = it * 256 + lane * 8;

        // a window: logical floats [lb+tb, lb+tb+35]; 9 swizzled LDS.128
        float aw[36];
#pragma unroll
        for (int j = 0; j < 9; ++j) {
            float4 w = *reinterpret_cast<const float4*>(
                a_b + swz((lb + tb + 4 * j) * 4));
            aw[4 * j + 0] = w.x; aw[4 * j + 1] = w.y;
            aw[4 * j + 2] = w.z; aw[4 * j + 3] = w.w;
        }
        // b chunk: 8 floats, 2 swizzled LDS.128
        float bv[8];
        {
            float4 p = *reinterpret_cast<const float4*>(b_b + swz(tb * 4));
            float4 q = *reinterpret_cast<const float4*>(b_b + swz((tb + 4) * 4));
            bv[0] = p.x; bv[1] = p.y; bv[2] = p.z; bv[3] = p.w;
            bv[4] = q.x; bv[5] = q.y; bv[6] = q.z; bv[7] = q.w;
        }

        // 112 FFMA2 per lane-iter: lag pair (2j, 2j+1) x time k
#pragma unroll
        for (int k = 0; k < 8; ++k) {
            const unsigned long long bb = pack2(bv[k], bv[k]);
#pragma unroll
            for (int j = 0; j < LPW / 2; ++j) {
                fma2(acc[j], pack2(aw[2 * j + k], aw[2 * j + k + 1]), bb);
            }
        }
    }

    // Lane reduction (lanes split t), then lane 0 writes 28 lags.
    float res[LPW];
#pragma unroll
    for (int j = 0; j < LPW / 2; ++j) unpack2(acc[j], res[2 * j], res[2 * j + 1]);
#pragma unroll
    for (int j = 0; j < LPW; ++j) {
#pragma unroll
        for (int o = 16; o > 0; o >>= 1)
            res[j] += __shfl_xor_sync(0xffffffffu, res[j], o);
    }
    if (lane == 0) {
        float4* dst = reinterpret_cast<float4*>(g_raw + (size_t)c * RAWS + lb);
#pragma unroll
        for (int j = 0; j < LPW / 4; ++j)
            dst[j] = make_float4(res[4 * j], res[4 * j + 1],
                                 res[4 * j + 2], res[4 * j + 3]);
    }
}

// ---------------------------------------------------------------------------
// Stage 2: moving average over channels (window [c-10, c+9], zero-padded),
// then per-channel argmax|R| / max / min / tmax.
// Block = 16 channels; thread = lag; sliding-window ring buffer in registers
// (each raw row read ~2.2x instead of 20x).
// ---------------------------------------------------------------------------
#define CPB 16
__global__ __launch_bounds__(128)
void xcorr_stage2(float* __restrict__ out)
{
    __shared__ float sh[CPB][NLAGS + 1];
    const int c0  = blockIdx.x * CPB;
    const int tid = threadIdx.x;

    if (tid < NLAGS) {
        float ring[20];
        float s = 0.0f;
#pragma unroll
        for (int i = 0; i < CPB + 19; ++i) {
            const int ch = c0 - 10 + i;
            float x = 0.0f;
            if (ch >= 0 && ch < NCH) x = g_raw[(size_t)ch * RAWS + tid];
            s += x;
            if (i >= 20) s -= ring[i % 20];
            ring[i % 20] = x;
            const int cc = i - 19;
            if (cc >= 0) {
                const float m = s * (1.0f / 20.0f);
                sh[cc][tid] = m;
                out[(size_t)(c0 + cc) * NLAGS + tid] = m;
            }
        }
    }
    __syncthreads();

    const int warp = tid >> 5;
    const int lane = tid & 31;

    // Each warp reduces 4 of the 16 channels.
    for (int cc = warp; cc < CPB; cc += 4) {
        float bestAbs = -1.0f;
        int   bestIdx = 0;
        float bestVal = 0.0f;
        float vpos = -3.402823466e38f;
        float vneg =  3.402823466e38f;

        for (int l = lane; l < NLAGS; l += 32) {
            const float v  = sh[cc][l];
            const float av = fabsf(v);
            if (av > bestAbs) { bestAbs = av; bestIdx = l; bestVal = v; }
            vpos = fmaxf(vpos, v);
            vneg = fminf(vneg, v);
        }
#pragma unroll
        for (int o = 16; o > 0; o >>= 1) {
            const float oa = __shfl_down_sync(0xffffffffu, bestAbs, o);
            const int   oi = __shfl_down_sync(0xffffffffu, bestIdx, o);
            const float ov = __shfl_down_sync(0xffffffffu, bestVal, o);
            if (oa > bestAbs || (oa == bestAbs && oi < bestIdx)) {
                bestAbs = oa; bestIdx = oi; bestVal = ov;
            }
            vpos = fmaxf(vpos, __shfl_down_sync(0xffffffffu, vpos, o));
            vneg = fminf(vneg, __shfl_down_sync(0xffffffffu, vneg, o));
        }

        if (lane == 0) {
            const int   ch    = c0 + cc;
            const float vside = (bestVal >= 0.0f) ? vneg : vpos;
            out[(size_t)XCOR_N + ch]           = bestVal;
            out[(size_t)XCOR_N + NCH + ch]     = vside;
            out[(size_t)XCOR_N + 2 * NCH + ch] = (float)(bestIdx - 51) * 0.01f;
        }
    }
}

// ---------------------------------------------------------------------------
// kernel_launch: inputs: data1 (f32, NC*NT), data2 (f32, NC*NT), event1,
// event2 (i32, unused by reference).
// ---------------------------------------------------------------------------
extern "C" void kernel_launch(void* const* d_in, const int* in_sizes, int n_in,
                              void* d_out, int out_size)
{
    const float* data1 = (const float*)d_in[0];
    const float* data2 = (const float*)d_in[1];
    float* out = (float*)d_out;

    xcorr_stage1<<<NCH, 128>>>(data1, data2);
    xcorr_stage2<<<NCH / CPB, 128>>>(out);
}